// round 4
// baseline (speedup 1.0000x reference)
#include <cuda_runtime.h>
#include <math.h>

#define B_ 128
#define T_ 512
#define D_ 512
#define U_ 512
#define N3 1536
#define RCTAS 128

typedef unsigned long long ull;

// ---- device scratch (static; allocation APIs banned) ----
__device__ float g_xproj[(size_t)T_ * B_ * N3];   // [t][b][n]
__device__ float g_h[2][U_ * B_];                 // [u][b]
__device__ float g_rh[U_ * B_];                   // [u][b]  (r*h)
__device__ float g_attnT[T_ * B_];                // [t][b]
__device__ unsigned g_bar;

// ---- helpers ----
__device__ __forceinline__ void cp16(float* sdst, const float* gsrc) {
    unsigned s = (unsigned)__cvta_generic_to_shared(sdst);
    asm volatile("cp.async.cg.shared.global [%0], [%1], 16;" :: "r"(s), "l"(gsrc));
}
template<int N> __device__ __forceinline__ void cpwait() {
    asm volatile("cp.async.wait_group %0;" :: "n"(N));
}
__device__ __forceinline__ ull pk2(float lo, float hi) {
    ull r; asm("mov.b64 %0, {%1, %2};" : "=l"(r) : "f"(lo), "f"(hi)); return r;
}
__device__ __forceinline__ float plo(ull v) {
    float a, b; asm("mov.b64 {%0, %1}, %2;" : "=f"(a), "=f"(b) : "l"(v)); return a;
}
__device__ __forceinline__ float phi(ull v) {
    float a, b; asm("mov.b64 {%0, %1}, %2;" : "=f"(a), "=f"(b) : "l"(v)); return b;
}
__device__ __forceinline__ void fma2(ull& d, ull a, ull b) {
    asm("fma.rn.f32x2 %0, %1, %2, %0;" : "+l"(d) : "l"(a), "l"(b));
}
__device__ __forceinline__ unsigned ldbar() {
    unsigned v;
    asm volatile("ld.acquire.gpu.global.u32 %0, [%1];" : "=r"(v) : "l"(&g_bar));
    return v;
}
__device__ __forceinline__ float hsig(float x) {
    return fminf(fmaxf(0.2f * x + 0.5f, 0.0f), 1.0f);
}

// ---- init ----
__global__ void init_k(const float* __restrict__ attn) {
    int i = blockIdx.x * 256 + threadIdx.x;
    if (i < U_ * B_) g_h[0][i] = 0.0f;
    if (i < T_ * B_) { int b = i >> 9, t = i & 511; g_attnT[t * B_ + b] = attn[i]; }
    if (i == 0) g_bar = 0u;
}

// ---- x_proj GEMM: g_xproj[t][b][n] = inputs[b][t][:] . W[:,n] + bias[n] ----
__global__ void __launch_bounds__(256) xproj_k(const float* __restrict__ A,
                                               const float* __restrict__ W,
                                               const float* __restrict__ bias) {
    __shared__ float As[16][132];
    __shared__ float Bs[16][132];
    const int tid = threadIdx.x;
    const int m0 = blockIdx.x * 128, n0 = blockIdx.y * 128;
    const int tx = tid & 15, ty = tid >> 4;
    ull acc[8][4];
    #pragma unroll
    for (int i = 0; i < 8; i++)
        #pragma unroll
        for (int j = 0; j < 4; j++) acc[i][j] = 0ull;

    for (int kt = 0; kt < D_; kt += 16) {
        {   // A tile 128x16 -> As[k][m] (transposed)
            int r = tid >> 1, c = (tid & 1) * 8;
            const float* src = A + (size_t)(m0 + r) * D_ + kt + c;
            float4 v0 = *(const float4*)(src);
            float4 v1 = *(const float4*)(src + 4);
            As[c + 0][r] = v0.x; As[c + 1][r] = v0.y; As[c + 2][r] = v0.z; As[c + 3][r] = v0.w;
            As[c + 4][r] = v1.x; As[c + 5][r] = v1.y; As[c + 6][r] = v1.z; As[c + 7][r] = v1.w;
        }
        {   // B tile 16x128
            int r = tid >> 5, c = (tid & 31) * 4;
            #pragma unroll
            for (int j = 0; j < 2; j++)
                *(float4*)&Bs[r + j * 8][c] = *(const float4*)(W + (size_t)(kt + r + j * 8) * N3 + n0 + c);
        }
        __syncthreads();
        #pragma unroll
        for (int k = 0; k < 16; k++) {
            float av[8];
            *(float4*)(av)     = *(float4*)&As[k][ty * 8];
            *(float4*)(av + 4) = *(float4*)&As[k][ty * 8 + 4];
            ulonglong2 b01 = *(ulonglong2*)&Bs[k][tx * 8];
            ulonglong2 b23 = *(ulonglong2*)&Bs[k][tx * 8 + 4];
            #pragma unroll
            for (int i = 0; i < 8; i++) {
                ull ad = pk2(av[i], av[i]);
                fma2(acc[i][0], ad, b01.x);
                fma2(acc[i][1], ad, b01.y);
                fma2(acc[i][2], ad, b23.x);
                fma2(acc[i][3], ad, b23.y);
            }
        }
        __syncthreads();
    }
    #pragma unroll
    for (int i = 0; i < 8; i++) {
        int m = m0 + ty * 8 + i, bb = m >> 9, t = m & 511;
        float* dst = g_xproj + (size_t)(t * B_ + bb) * N3 + n0 + tx * 8;
        float o[8];
        #pragma unroll
        for (int j = 0; j < 4; j++) {
            o[2 * j]     = plo(acc[i][j]) + bias[n0 + tx * 8 + 2 * j];
            o[2 * j + 1] = phi(acc[i][j]) + bias[n0 + tx * 8 + 2 * j + 1];
        }
        *(float4*)(dst)     = *(float4*)(o);
        *(float4*)(dst + 4) = *(float4*)(o + 4);
    }
}

// ---- persistent two-phase GRU recurrence ----
// 128 CTAs x 256 threads. thread = (b = tid&127, kk = tid>>7). CTA owns u in [u0,u0+4).
// smem: sRzr[512][4] ull (z/r col-pairs), sRh[512][2] ull, sS[2][64*128] float staging.
#define REC_SMEM ((3072 * 8) + (2 * 8192 * 4))

__device__ __forceinline__ void stage64(float* dst, const float* src, int tid) {
    #pragma unroll
    for (int j = 0; j < 8; j++) {
        int idx = (tid + j * 256) * 4;
        cp16(dst + idx, src + idx);
    }
    asm volatile("cp.async.commit_group;");
}

__global__ void __launch_bounds__(256, 1) rec_k(const float* __restrict__ RK,
                                                float* __restrict__ out) {
    extern __shared__ ull smb[];
    ull* sRzr = smb;                       // 2048 ull
    ull* sRh  = smb + 2048;                // 1024 ull
    float* sS = (float*)(smb + 3072);      // 2 x 8192 floats
    const int tid = threadIdx.x;
    const int b = tid & 127, kk = tid >> 7;
    const int u0 = blockIdx.x * 4;
    const int up = u0 + 2 * kk;            // this thread's u-pair base

    // preload R columns (packed pairs)
    for (int k = tid; k < 512; k += 256) {
        const float* rk = RK + (size_t)k * N3;
        sRzr[k * 4 + 0] = pk2(rk[u0],        rk[u0 + 1]);
        sRzr[k * 4 + 1] = pk2(rk[512 + u0],  rk[512 + u0 + 1]);
        sRzr[k * 4 + 2] = pk2(rk[u0 + 2],    rk[u0 + 3]);
        sRzr[k * 4 + 3] = pk2(rk[512 + u0 + 2], rk[512 + u0 + 3]);
        sRh[k * 2 + 0]  = pk2(rk[1024 + u0],     rk[1024 + u0 + 1]);
        sRh[k * 2 + 1]  = pk2(rk[1024 + u0 + 2], rk[1024 + u0 + 3]);
    }
    __syncthreads();

    int cur = 0;
    for (int t = 0; t < T_; t++) {
        const float* hsrc = g_h[cur];

        // ---------- phase 1: az, ar = h @ [Rz|Rr] cols ----------
        stage64(sS, hsrc, tid);
        ull az = 0ull, ar = 0ull;
        for (int c = 0; c < 8; c++) {
            if (c < 7) { stage64(sS + ((c + 1) & 1) * 8192, hsrc + (c + 1) * 8192, tid); cpwait<1>(); }
            else cpwait<0>();
            __syncthreads();
            const float* hb = sS + (c & 1) * 8192;
            const ull* rr = sRzr + (size_t)c * 64 * 4 + kk * 2;
            #pragma unroll 16
            for (int k = 0; k < 64; k++) {
                float hv = hb[k * 128 + b];
                ull hd = pk2(hv, hv);
                ulonglong2 zr = *(const ulonglong2*)(rr + k * 4);
                fma2(az, hd, zr.x);
                fma2(ar, hd, zr.y);
            }
            __syncthreads();
        }

        const float* xp = g_xproj + ((size_t)t * B_ + b) * N3 + up;
        float2 xz = *(const float2*)(xp);
        float2 xr = *(const float2*)(xp + 512);
        float2 xh = *(const float2*)(xp + 1024);
        float hp0 = hsrc[up * 128 + b];
        float hp1 = hsrc[(up + 1) * 128 + b];
        float z0 = hsig(xz.x + plo(az)), z1 = hsig(xz.y + phi(az));
        float r0 = hsig(xr.x + plo(ar)), r1 = hsig(xr.y + phi(ar));
        g_rh[up * 128 + b]       = r0 * hp0;
        g_rh[(up + 1) * 128 + b] = r1 * hp1;

        __threadfence();
        __syncthreads();
        if (tid == 0) {
            atomicAdd(&g_bar, 1u);
            unsigned tgt = (unsigned)(2 * t + 1) * RCTAS;
            while (ldbar() < tgt) { }
        }
        __syncthreads();

        // ---------- phase 2: ah = (r.h) @ Rh cols ----------
        stage64(sS, g_rh, tid);
        ull ah = 0ull;
        for (int c = 0; c < 8; c++) {
            if (c < 7) { stage64(sS + ((c + 1) & 1) * 8192, g_rh + (c + 1) * 8192, tid); cpwait<1>(); }
            else cpwait<0>();
            __syncthreads();
            const float* hb = sS + (c & 1) * 8192;
            const ull* rr = sRh + (size_t)c * 64 * 2 + kk;
            #pragma unroll 16
            for (int k = 0; k < 64; k++) {
                float rv = hb[k * 128 + b];
                ull rd = pk2(rv, rv);
                fma2(ah, rd, rr[k * 2]);
            }
            __syncthreads();
        }

        float a = g_attnT[t * B_ + b];
        float hh0 = tanhf(xh.x + plo(ah));
        float hh1 = tanhf(xh.y + phi(ah));
        float hn0 = z0 * hp0 + (1.0f - z0) * hh0;
        float hn1 = z1 * hp1 + (1.0f - z1) * hh1;
        hn0 = a * hn0 + (1.0f - a) * hp0;
        hn1 = a * hn1 + (1.0f - a) * hp1;
        float* hd = g_h[cur ^ 1];
        hd[up * 128 + b]       = hn0;
        hd[(up + 1) * 128 + b] = hn1;
        if (t == T_ - 1) {
            out[b * U_ + up]     = hn0;
            out[b * U_ + up + 1] = hn1;
        }

        __threadfence();
        __syncthreads();
        if (tid == 0) {
            atomicAdd(&g_bar, 1u);
            unsigned tgt = (unsigned)(2 * t + 2) * RCTAS;
            while (ldbar() < tgt) { }
        }
        __syncthreads();
        cur ^= 1;
    }
}

extern "C" void kernel_launch(void* const* d_in, const int* in_sizes, int n_in,
                              void* d_out, int out_size) {
    const float* inputs = (const float*)d_in[0];
    const float* attn   = (const float*)d_in[1];
    const float* Wk     = (const float*)d_in[2];
    const float* RK     = (const float*)d_in[3];
    const float* bias   = (const float*)d_in[4];
    cudaFuncSetAttribute(rec_k, cudaFuncAttributeMaxDynamicSharedMemorySize, REC_SMEM);
    init_k<<<256, 256>>>(attn);
    xproj_k<<<dim3(512, 12), 256>>>(inputs, Wk, bias);
    rec_k<<<RCTAS, 256, REC_SMEM>>>(RK, (float*)d_out);
}